// round 12
// baseline (speedup 1.0000x reference)
#include <cuda_runtime.h>
#include <cuda_fp16.h>
#include <cstdint>

#define SS 8
#define NN 512
#define CC 128
#define HH 128

// Scratch: channels-last fp16 fmap pyramid per plane + fp32 scaled init feats.
__device__ __half g_P0[(size_t)3 * SS * HH * HH * CC];     // [3*S][128][128][C]
__device__ __half g_P1[(size_t)3 * SS * 64 * 64 * CC];
__device__ __half g_P2[(size_t)3 * SS * 32 * 32 * CC];
__device__ __half g_P3[(size_t)3 * SS * 16 * 16 * CC];
__device__ float  g_T [(size_t)3 * NN * CC];               // t / sqrt(C), fp32

__device__ __forceinline__ float2 h2f(uint32_t u) {
    return __half22float2(*(const __half2*)&u);
}

// ---------------------------------------------------------------------------
// Fused transpose + L1 pool. Tile = 32 channels x (2 rows x 16 px).
// ---------------------------------------------------------------------------
__global__ void __launch_bounds__(256) transposeL1_kernel(const float* __restrict__ fxy,
                                                          const float* __restrict__ fyz,
                                                          const float* __restrict__ fxz) {
    __shared__ float tile[32][33];    // [c][px], px = r*16 + j

    int ps = blockIdx.z;              // p*S + s
    int p = ps >> 3, s = ps & 7;
    const float* src = (p == 0 ? fxy : (p == 1 ? fyz : fxz)) + (size_t)s * CC * HH * HH;

    int c0 = blockIdx.y * 32;
    int mt = blockIdx.x;              // 0..511
    int rp = mt >> 3;                 // row pair 0..63
    int xt = (mt & 7) << 4;           // px base within row
    int t = threadIdx.x, lane = t & 31, w = t >> 5;

#pragma unroll
    for (int k = 0; k < 4; k++) {
        int c = w * 4 + k;
        int r = lane >> 4;
        int j = lane & 15;
        tile[c][r * 16 + j] = src[(size_t)(c0 + c) * (HH * HH) + (2 * rp + r) * HH + xt + j];
    }
    __syncthreads();

    {
        __half* d0 = g_P0 + (size_t)ps * HH * HH * CC;
#pragma unroll
        for (int k = 0; k < 4; k++) {
            int px = w * 4 + k;
            int r = px >> 4, j = px & 15;
            float v = tile[lane][px];
            size_t gpix = (size_t)(2 * rp + r) * HH + xt + j;
            d0[gpix * CC + c0 + lane] = __float2half(v);
        }
    }

    {
        __half* d1 = g_P1 + (size_t)ps * 64 * 64 * CC;
        int j1 = w;
        float v = (tile[lane][2 * j1] + tile[lane][2 * j1 + 1]
                 + tile[lane][16 + 2 * j1] + tile[lane][16 + 2 * j1 + 1]) * 0.25f;
        size_t gpix1 = (size_t)rp * 64 + (xt >> 1) + j1;
        d1[gpix1 * CC + c0 + lane] = __float2half(v);
    }
}

// ---------------------------------------------------------------------------
// Fused L2 + L3 pools from L1. Block = 4x4 L1-pixel tile x all 128 channels.
// ---------------------------------------------------------------------------
__global__ void __launch_bounds__(256) pool23_kernel() {
    __shared__ float s1[16][CC];
    __shared__ float s2[4][CC];

    int ps = blockIdx.y;
    int b = blockIdx.x;
    int by = b >> 4, bx = b & 15;
    const __half* src1 = g_P1 + (size_t)ps * 64 * 64 * CC;
    int t = threadIdx.x;

    {
        int px = t >> 4;
        int cg = (t & 15) * 8;
        int ly = px >> 2, lx = px & 3;
        const __half* q = src1 + ((size_t)((by * 4 + ly) * 64 + bx * 4 + lx)) * CC + cg;
        uint4 r = __ldcg((const uint4*)q);
        float2 f;
        f = h2f(r.x); s1[px][cg + 0] = f.x; s1[px][cg + 1] = f.y;
        f = h2f(r.y); s1[px][cg + 2] = f.x; s1[px][cg + 3] = f.y;
        f = h2f(r.z); s1[px][cg + 4] = f.x; s1[px][cg + 5] = f.y;
        f = h2f(r.w); s1[px][cg + 6] = f.x; s1[px][cg + 7] = f.y;
    }
    __syncthreads();

    {
        __half* d2 = g_P2 + (size_t)ps * 32 * 32 * CC;
#pragma unroll
        for (int it = 0; it < 2; it++) {
            int lin = it * 256 + t;
            int opx = lin >> 7;
            int c = lin & 127;
            int oy = opx >> 1, ox = opx & 1;
            int pA = (2 * oy) * 4 + 2 * ox;
            float v = (s1[pA][c] + s1[pA + 1][c] + s1[pA + 4][c] + s1[pA + 5][c]) * 0.25f;
            s2[opx][c] = v;
            d2[((size_t)((by * 2 + oy) * 32 + bx * 2 + ox)) * CC + c] = __float2half(v);
        }
    }
    __syncthreads();

    if (t < 128) {
        __half* d3 = g_P3 + (size_t)ps * 16 * 16 * CC;
        float v = (s2[0][t] + s2[1][t] + s2[2][t] + s2[3][t]) * 0.25f;
        d3[((size_t)(by * 16 + bx)) * CC + t] = __float2half(v);
    }
}

// ---------------------------------------------------------------------------
// Init track features (fp32 accumulate from fp16 P0), pre-scaled 1/sqrt(C)
// ---------------------------------------------------------------------------
__global__ void init_kernel(const float* __restrict__ coords,
                            const int* __restrict__ qt) {
    int n = blockIdx.x, p = blockIdx.y, c = threadIdx.x;
    float x = coords[n * 3 + 0], y = coords[n * 3 + 1], z = coords[n * 3 + 2];
    float u = (p == 0) ? x : (p == 1 ? y : x);
    float v = (p == 0) ? y : z;
    int f = qt[n];
    const __half* base = g_P0 + (size_t)(p * SS + f) * HH * HH * CC;

    u = fminf(fmaxf(u, 0.f), (float)(HH - 1));
    v = fminf(fmaxf(v, 0.f), (float)(HH - 1));
    int x0 = min(max((int)floorf(u), 0), HH - 2);
    int y0 = min(max((int)floorf(v), 0), HH - 2);
    float wx = u - (float)x0, wy = v - (float)y0;

    const __half* b00 = base + ((size_t)(y0 * HH + x0) << 7);
    float v00 = __half2float(b00[c]);
    float v01 = __half2float(b00[CC + c]);
    float v10 = __half2float(b00[(HH << 7) + c]);
    float v11 = __half2float(b00[(HH << 7) + CC + c]);
    float val = v00 * (1.f - wx) * (1.f - wy) + v01 * wx * (1.f - wy)
              + v10 * (1.f - wx) * wy + v11 * wx * wy;
    g_T[(size_t)(p * NN + n) * CC + c] = val * 0.08838834764831845f; // 1/sqrt(128)
}

// ---------------------------------------------------------------------------
// Grid phase for one level. STREAM=true -> __ldcg (L2-only, keeps L1 free for
// the high-reuse coarse levels); STREAM=false -> default cached loads.
// ---------------------------------------------------------------------------
template <bool STREAM>
__device__ __forceinline__ void grid_phase(const __half* base, int Wl,
                                           int bx, int by, int li, int hp,
                                           __half2 t0, __half2 t1, __half2 t2, __half2 t3,
                                           float* Grow) {
    int co0 = min(max(bx - 3 + hp, 0), Wl - 1) * CC;
    int co1 = min(max(bx - 1 + hp, 0), Wl - 1) * CC;
    int co2 = min(max(bx + 1 + hp, 0), Wl - 1) * CC;
    int co3 = min(max(bx + 3 + hp, 0), Wl - 1) * CC;
    const __half* lb = base + (li << 3);
    const int rowStride = Wl * CC;

#pragma unroll
    for (int r = 0; r < 8; r++) {
        int gy = min(max(by - 3 + r, 0), Wl - 1);
        const __half* rb = lb + gy * rowStride;
#pragma unroll
        for (int j = 0; j < 4; j++) {
            int co = (j == 0) ? co0 : (j == 1) ? co1 : (j == 2) ? co2 : co3;
            union { uint4 u4; __half2 h[4]; } rw;
            if (STREAM) rw.u4 = __ldcg((const uint4*)(rb + co));
            else        rw.u4 = *(const uint4*)(rb + co);
            __half2 acc = __hmul2(rw.h[0], t0);
            acc = __hfma2(rw.h[1], t1, acc);
            acc = __hfma2(rw.h[2], t2, acc);
            acc = __hfma2(rw.h[3], t3, acc);
            float dv = __low2float(acc) + __high2float(acc);
            dv += __shfl_xor_sync(0xffffffffu, dv, 8);
            dv += __shfl_xor_sync(0xffffffffu, dv, 4);
            dv += __shfl_xor_sync(0xffffffffu, dv, 2);
            dv += __shfl_xor_sync(0xffffffffu, dv, 1);
            if (li == 0) Grow[r * 8 + 2 * j + hp] = dv;
        }
    }
}

// ---------------------------------------------------------------------------
// Main: block = (n, s, p). Warp w = pyramid level w. L0/L1 loads stream via
// L2 only; L2/L3 loads cache in L1 (cross-block frame reuse).
// ---------------------------------------------------------------------------
__global__ void __launch_bounds__(128) main_kernel(const float* __restrict__ coords,
                                                   float* __restrict__ out) {
    int n = blockIdx.x;
    int s = 7 - blockIdx.y;                  // flipped traversal (L2-tail reuse)
    int p = 2 - blockIdx.z;
    int tid = threadIdx.x, lane = tid & 31, w = tid >> 5;
    int ps = p * SS + s;

    const float* cc = coords + (size_t)(s * NN + n) * 3;
    float x = cc[0], y = cc[1], z = cc[2];
    float u = (p == 0) ? x : (p == 1 ? y : x);
    float v = (p == 0) ? y : z;

    __shared__ float sT[CC];
    __shared__ float G[4][64];
    sT[tid] = g_T[(size_t)(p * NN + n) * CC + tid];
    __syncthreads();

    int li = lane & 15;
    int hp = lane >> 4;
    float4 tA = ((const float4*)sT)[li * 2];
    float4 tB = ((const float4*)sT)[li * 2 + 1];
    __half2 t0 = __floats2half2_rn(tA.x, tA.y);
    __half2 t1 = __floats2half2_rn(tA.z, tA.w);
    __half2 t2 = __floats2half2_rn(tB.x, tB.y);
    __half2 t3 = __floats2half2_rn(tB.z, tB.w);

    const __half* base0 = g_P0 + (size_t)ps * HH * HH * CC;
    const __half* base1 = g_P1 + (size_t)ps * 64 * 64 * CC;
    const __half* base2 = g_P2 + (size_t)ps * 32 * 32 * CC;
    const __half* base3 = g_P3 + (size_t)ps * 16 * 16 * CC;

    // ---- grid phase: warp w handles level w ----
    {
        const int l = w;
        const int Wl = HH >> l;
        const float sc = 1.0f / (float)(1 << l);
        const __half* base = (l == 0) ? base0 : (l == 1) ? base1 : (l == 2) ? base2 : base3;

        float cx = u * sc, cy = v * sc;
        int bx = (int)floorf(cx), by = (int)floorf(cy);

        if (l < 2) grid_phase<true >(base, Wl, bx, by, li, hp, t0, t1, t2, t3, G[l]);
        else       grid_phase<false>(base, Wl, bx, by, li, hp, t0, t1, t2, t3, G[l]);
    }
    __syncthreads();

    float* ob = out + ((size_t)s * NN + n) * 972;

    // ---- tap phase: 196 taps over 128 threads ----
#pragma unroll
    for (int t = tid; t < 196; t += 128) {
        int l = t / 49, k = t % 49;
        int Wl = HH >> l;
        float sc = (l == 0) ? 1.f : (l == 1) ? 0.5f : (l == 2) ? 0.25f : 0.125f;
        float cx = u * sc, cy = v * sc;
        int bx = (int)floorf(cx), by = (int)floorf(cy);
        int kx = k % 7, ky = k / 7;
        float xs = fminf(fmaxf(cx + (float)(kx - 3), 0.f), (float)(Wl - 1));
        float ys = fminf(fmaxf(cy + (float)(ky - 3), 0.f), (float)(Wl - 1));
        int x0 = min(max((int)floorf(xs), 0), Wl - 2);
        int y0 = min(max((int)floorf(ys), 0), Wl - 2);
        float wx = xs - (float)x0, wy = ys - (float)y0;
        int j = x0 - bx + 3;   // in [0,6], j+1 <= 7 (clamp cases verified)
        int i = y0 - by + 3;
        float g00 = G[l][i * 8 + j];
        float g01 = G[l][i * 8 + j + 1];
        float g10 = G[l][i * 8 + 8 + j];
        float g11 = G[l][i * 8 + 8 + j + 1];
        ob[p * 196 + t] = g00 * (1.f - wx) * (1.f - wy) + g01 * wx * (1.f - wy)
                        + g10 * (1.f - wx) * wy + g11 * wx * wy;
    }

    // ---- full-res feature bilinear sample (thread = channel) ----
    {
        float xs = fminf(fmaxf(u, 0.f), (float)(HH - 1));
        float ys = fminf(fmaxf(v, 0.f), (float)(HH - 1));
        int x0 = min(max((int)floorf(xs), 0), HH - 2);
        int y0 = min(max((int)floorf(ys), 0), HH - 2);
        float wx = xs - (float)x0, wy = ys - (float)y0;
        const __half* b00 = base0 + ((size_t)(y0 * HH + x0) << 7);
        float v00 = __half2float(b00[tid]);
        float v01 = __half2float(b00[CC + tid]);
        float v10 = __half2float(b00[(HH << 7) + tid]);
        float v11 = __half2float(b00[(HH << 7) + CC + tid]);
        ob[588 + p * CC + tid] = v00 * (1.f - wx) * (1.f - wy) + v01 * wx * (1.f - wy)
                               + v10 * (1.f - wx) * wy + v11 * wx * wy;
    }
}

// ---------------------------------------------------------------------------
extern "C" void kernel_launch(void* const* d_in, const int* in_sizes, int n_in,
                              void* d_out, int out_size) {
    const float* fxy    = (const float*)d_in[0];
    const float* fyz    = (const float*)d_in[1];
    const float* fxz    = (const float*)d_in[2];
    const float* coords = (const float*)d_in[3];
    const int*   qt     = (const int*)d_in[4];
    float* out = (float*)d_out;

    // 1) fused transpose + L0/L1 (channels-last fp16)
    {
        dim3 grid(512, CC / 32, 3 * SS);
        transposeL1_kernel<<<grid, 256>>>(fxy, fyz, fxz);
    }
    // 2) fused L2 + L3 pools
    {
        dim3 grid(256, 3 * SS);
        pool23_kernel<<<grid, 256>>>();
    }
    // 3) init track features
    {
        dim3 grid(NN, 3);
        init_kernel<<<grid, CC>>>(coords, qt);
    }
    // 4) main correlation + feature sampling
    {
        dim3 grid(NN, SS, 3);
        main_kernel<<<grid, 128>>>(coords, out);
    }
}

// round 14
// speedup vs baseline: 1.0714x; 1.0714x over previous
#include <cuda_runtime.h>
#include <cuda_fp16.h>
#include <cstdint>

#define SS 8
#define NN 512
#define CC 128
#define HH 128

// Scratch: channels-last fp16 fmap pyramid per plane + fp32 scaled init feats.
__device__ __half g_P0[(size_t)3 * SS * HH * HH * CC];     // [3*S][128][128][C]
__device__ __half g_P1[(size_t)3 * SS * 64 * 64 * CC];
__device__ __half g_P2[(size_t)3 * SS * 32 * 32 * CC];
__device__ __half g_P3[(size_t)3 * SS * 16 * 16 * CC];
__device__ float  g_T [(size_t)3 * NN * CC];               // t / sqrt(C), fp32

__device__ __forceinline__ float2 h2f(uint32_t u) {
    return __half22float2(*(const __half2*)&u);
}

// ---------------------------------------------------------------------------
// Fused transpose + L1 pool. Tile = 32 channels x (2 rows x 16 px).
// ---------------------------------------------------------------------------
__global__ void __launch_bounds__(256) transposeL1_kernel(const float* __restrict__ fxy,
                                                          const float* __restrict__ fyz,
                                                          const float* __restrict__ fxz) {
    __shared__ float tile[32][33];    // [c][px], px = r*16 + j

    int ps = blockIdx.z;              // p*S + s
    int p = ps >> 3, s = ps & 7;
    const float* src = (p == 0 ? fxy : (p == 1 ? fyz : fxz)) + (size_t)s * CC * HH * HH;

    int c0 = blockIdx.y * 32;
    int mt = blockIdx.x;              // 0..511
    int rp = mt >> 3;                 // row pair 0..63
    int xt = (mt & 7) << 4;           // px base within row
    int t = threadIdx.x, lane = t & 31, w = t >> 5;

#pragma unroll
    for (int k = 0; k < 4; k++) {
        int c = w * 4 + k;
        int r = lane >> 4;
        int j = lane & 15;
        tile[c][r * 16 + j] = src[(size_t)(c0 + c) * (HH * HH) + (2 * rp + r) * HH + xt + j];
    }
    __syncthreads();

    {
        __half* d0 = g_P0 + (size_t)ps * HH * HH * CC;
#pragma unroll
        for (int k = 0; k < 4; k++) {
            int px = w * 4 + k;
            int r = px >> 4, j = px & 15;
            float v = tile[lane][px];
            size_t gpix = (size_t)(2 * rp + r) * HH + xt + j;
            d0[gpix * CC + c0 + lane] = __float2half(v);
        }
    }

    {
        __half* d1 = g_P1 + (size_t)ps * 64 * 64 * CC;
        int j1 = w;
        float v = (tile[lane][2 * j1] + tile[lane][2 * j1 + 1]
                 + tile[lane][16 + 2 * j1] + tile[lane][16 + 2 * j1 + 1]) * 0.25f;
        size_t gpix1 = (size_t)rp * 64 + (xt >> 1) + j1;
        d1[gpix1 * CC + c0 + lane] = __float2half(v);
    }
}

// ---------------------------------------------------------------------------
// Fused L2 + L3 pools from L1. Block = 4x4 L1-pixel tile x all 128 channels.
// ---------------------------------------------------------------------------
__global__ void __launch_bounds__(256) pool23_kernel() {
    __shared__ float s1[16][CC];
    __shared__ float s2[4][CC];

    int ps = blockIdx.y;
    int b = blockIdx.x;
    int by = b >> 4, bx = b & 15;
    const __half* src1 = g_P1 + (size_t)ps * 64 * 64 * CC;
    int t = threadIdx.x;

    {
        int px = t >> 4;
        int cg = (t & 15) * 8;
        int ly = px >> 2, lx = px & 3;
        const __half* q = src1 + ((size_t)((by * 4 + ly) * 64 + bx * 4 + lx)) * CC + cg;
        uint4 r = *(const uint4*)q;
        float2 f;
        f = h2f(r.x); s1[px][cg + 0] = f.x; s1[px][cg + 1] = f.y;
        f = h2f(r.y); s1[px][cg + 2] = f.x; s1[px][cg + 3] = f.y;
        f = h2f(r.z); s1[px][cg + 4] = f.x; s1[px][cg + 5] = f.y;
        f = h2f(r.w); s1[px][cg + 6] = f.x; s1[px][cg + 7] = f.y;
    }
    __syncthreads();

    {
        __half* d2 = g_P2 + (size_t)ps * 32 * 32 * CC;
#pragma unroll
        for (int it = 0; it < 2; it++) {
            int lin = it * 256 + t;
            int opx = lin >> 7;
            int c = lin & 127;
            int oy = opx >> 1, ox = opx & 1;
            int pA = (2 * oy) * 4 + 2 * ox;
            float v = (s1[pA][c] + s1[pA + 1][c] + s1[pA + 4][c] + s1[pA + 5][c]) * 0.25f;
            s2[opx][c] = v;
            d2[((size_t)((by * 2 + oy) * 32 + bx * 2 + ox)) * CC + c] = __float2half(v);
        }
    }
    __syncthreads();

    if (t < 128) {
        __half* d3 = g_P3 + (size_t)ps * 16 * 16 * CC;
        float v = (s2[0][t] + s2[1][t] + s2[2][t] + s2[3][t]) * 0.25f;
        d3[((size_t)(by * 16 + bx)) * CC + t] = __float2half(v);
    }
}

// ---------------------------------------------------------------------------
// Init track features (fp32 accumulate from fp16 P0), pre-scaled 1/sqrt(C)
// ---------------------------------------------------------------------------
__global__ void init_kernel(const float* __restrict__ coords,
                            const int* __restrict__ qt) {
    int n = blockIdx.x, p = blockIdx.y, c = threadIdx.x;
    float x = coords[n * 3 + 0], y = coords[n * 3 + 1], z = coords[n * 3 + 2];
    float u = (p == 0) ? x : (p == 1 ? y : x);
    float v = (p == 0) ? y : z;
    int f = qt[n];
    const __half* base = g_P0 + (size_t)(p * SS + f) * HH * HH * CC;

    u = fminf(fmaxf(u, 0.f), (float)(HH - 1));
    v = fminf(fmaxf(v, 0.f), (float)(HH - 1));
    int x0 = min(max((int)floorf(u), 0), HH - 2);
    int y0 = min(max((int)floorf(v), 0), HH - 2);
    float wx = u - (float)x0, wy = v - (float)y0;

    const __half* b00 = base + ((size_t)(y0 * HH + x0) << 7);
    float v00 = __half2float(b00[c]);
    float v01 = __half2float(b00[CC + c]);
    float v10 = __half2float(b00[(HH << 7) + c]);
    float v11 = __half2float(b00[(HH << 7) + CC + c]);
    float val = v00 * (1.f - wx) * (1.f - wy) + v01 * wx * (1.f - wy)
              + v10 * (1.f - wx) * wy + v11 * wx * wy;
    g_T[(size_t)(p * NN + n) * CC + c] = val * 0.08838834764831845f; // 1/sqrt(128)
}

// ---------------------------------------------------------------------------
// Main: block = (n, s, p). Warp w = pyramid level w. Array-free hoisted
// addressing, HFMA2 half2 dot partials, FOLD-PAIR reduction: the 4 dots of
// one row share a single 5-shfl butterfly (classes land on lanes 0/4/8/12
// holding j = 0/2/1/3 respectively).
// ---------------------------------------------------------------------------
__global__ void __launch_bounds__(128) main_kernel(const float* __restrict__ coords,
                                                   float* __restrict__ out) {
    int n = blockIdx.x;
    int s = 7 - blockIdx.y;                  // flipped traversal (L2-tail reuse)
    int p = 2 - blockIdx.z;
    int tid = threadIdx.x, lane = tid & 31, w = tid >> 5;
    int ps = p * SS + s;

    const float* cc = coords + (size_t)(s * NN + n) * 3;
    float x = cc[0], y = cc[1], z = cc[2];
    float u = (p == 0) ? x : (p == 1 ? y : x);
    float v = (p == 0) ? y : z;

    __shared__ float sT[CC];
    __shared__ float G[4][64];
    sT[tid] = g_T[(size_t)(p * NN + n) * CC + tid];
    __syncthreads();

    int li = lane & 15;
    int hp = lane >> 4;                       // half-warp position parity
    float4 tA = ((const float4*)sT)[li * 2];  // channels li*8 .. li*8+7
    float4 tB = ((const float4*)sT)[li * 2 + 1];
    __half2 t0 = __floats2half2_rn(tA.x, tA.y);
    __half2 t1 = __floats2half2_rn(tA.z, tA.w);
    __half2 t2 = __floats2half2_rn(tB.x, tB.y);
    __half2 t3 = __floats2half2_rn(tB.z, tB.w);

    // result-lane bookkeeping for the folded reduction:
    // lanes li in {0,4,8,12} end up holding j = {0,2,1,3}
    int q = li >> 2;
    int jm = ((q & 1) << 1) | (q >> 1);
    int gcol = 2 * jm + hp;                   // G column this lane may write
    bool isRes = (li & 3) == 0;

    const __half* base0 = g_P0 + (size_t)ps * HH * HH * CC;
    const __half* base1 = g_P1 + (size_t)ps * 64 * 64 * CC;
    const __half* base2 = g_P2 + (size_t)ps * 32 * 32 * CC;
    const __half* base3 = g_P3 + (size_t)ps * 16 * 16 * CC;

    // ---- grid phase: warp w handles level w ----
    {
        const int l = w;
        const int Wl = HH >> l;
        const float sc = 1.0f / (float)(1 << l);
        const __half* base = (l == 0) ? base0 : (l == 1) ? base1 : (l == 2) ? base2 : base3;

        float cx = u * sc, cy = v * sc;
        int bx = (int)floorf(cx), by = (int)floorf(cy);

        // 4 named clamped column offsets for this half-warp (cols 2j+hp)
        int co0 = min(max(bx - 3 + hp, 0), Wl - 1) * CC;
        int co1 = min(max(bx - 1 + hp, 0), Wl - 1) * CC;
        int co2 = min(max(bx + 1 + hp, 0), Wl - 1) * CC;
        int co3 = min(max(bx + 3 + hp, 0), Wl - 1) * CC;
        const __half* lb = base + (li << 3);
        const int rowStride = Wl * CC;
        bool b8 = (li & 8) != 0, b4 = (li & 4) != 0;

#pragma unroll
        for (int r = 0; r < 8; r++) {
            int gy = min(max(by - 3 + r, 0), Wl - 1);
            const __half* rb = lb + gy * rowStride;

            union { uint4 u4; __half2 h[4]; } r0, r1, r2, r3;
            r0.u4 = *(const uint4*)(rb + co0);
            r1.u4 = *(const uint4*)(rb + co1);
            r2.u4 = *(const uint4*)(rb + co2);
            r3.u4 = *(const uint4*)(rb + co3);

            __half2 a0 = __hmul2(r0.h[0], t0);
            a0 = __hfma2(r0.h[1], t1, a0); a0 = __hfma2(r0.h[2], t2, a0); a0 = __hfma2(r0.h[3], t3, a0);
            __half2 a1 = __hmul2(r1.h[0], t0);
            a1 = __hfma2(r1.h[1], t1, a1); a1 = __hfma2(r1.h[2], t2, a1); a1 = __hfma2(r1.h[3], t3, a1);
            __half2 a2 = __hmul2(r2.h[0], t0);
            a2 = __hfma2(r2.h[1], t1, a2); a2 = __hfma2(r2.h[2], t2, a2); a2 = __hfma2(r2.h[3], t3, a2);
            __half2 a3 = __hmul2(r3.h[0], t0);
            a3 = __hfma2(r3.h[1], t1, a3); a3 = __hfma2(r3.h[2], t2, a3); a3 = __hfma2(r3.h[3], t3, a3);

            float d0 = __low2float(a0) + __high2float(a0);
            float d1 = __low2float(a1) + __high2float(a1);
            float d2 = __low2float(a2) + __high2float(a2);
            float d3 = __low2float(a3) + __high2float(a3);

            // fold-pair reduction over 16 lanes (xor < 16: half-warps independent)
            float sA = __shfl_xor_sync(0xffffffffu, b8 ? d0 : d1, 8);
            float aa = (b8 ? d1 : d0) + sA;
            float sB = __shfl_xor_sync(0xffffffffu, b8 ? d2 : d3, 8);
            float bb = (b8 ? d3 : d2) + sB;
            float sC = __shfl_xor_sync(0xffffffffu, b4 ? aa : bb, 4);
            float cval = (b4 ? bb : aa) + sC;
            cval += __shfl_xor_sync(0xffffffffu, cval, 2);
            cval += __shfl_xor_sync(0xffffffffu, cval, 1);

            if (isRes) G[l][r * 8 + gcol] = cval;
        }
    }
    __syncthreads();

    float* ob = out + ((size_t)s * NN + n) * 972;

    // ---- tap phase: 196 taps over 128 threads ----
#pragma unroll
    for (int t = tid; t < 196; t += 128) {
        int l = t / 49, k = t % 49;
        int Wl = HH >> l;
        float sc = (l == 0) ? 1.f : (l == 1) ? 0.5f : (l == 2) ? 0.25f : 0.125f;
        float cx = u * sc, cy = v * sc;
        int bx = (int)floorf(cx), by = (int)floorf(cy);
        int kx = k % 7, ky = k / 7;
        float xs = fminf(fmaxf(cx + (float)(kx - 3), 0.f), (float)(Wl - 1));
        float ys = fminf(fmaxf(cy + (float)(ky - 3), 0.f), (float)(Wl - 1));
        int x0 = min(max((int)floorf(xs), 0), Wl - 2);
        int y0 = min(max((int)floorf(ys), 0), Wl - 2);
        float wx = xs - (float)x0, wy = ys - (float)y0;
        int j = x0 - bx + 3;   // in [0,6], j+1 <= 7 (clamp cases verified)
        int i = y0 - by + 3;
        float g00 = G[l][i * 8 + j];
        float g01 = G[l][i * 8 + j + 1];
        float g10 = G[l][i * 8 + 8 + j];
        float g11 = G[l][i * 8 + 8 + j + 1];
        ob[p * 196 + t] = g00 * (1.f - wx) * (1.f - wy) + g01 * wx * (1.f - wy)
                        + g10 * (1.f - wx) * wy + g11 * wx * wy;
    }

    // ---- full-res feature bilinear sample (thread = channel) ----
    {
        float xs = fminf(fmaxf(u, 0.f), (float)(HH - 1));
        float ys = fminf(fmaxf(v, 0.f), (float)(HH - 1));
        int x0 = min(max((int)floorf(xs), 0), HH - 2);
        int y0 = min(max((int)floorf(ys), 0), HH - 2);
        float wx = xs - (float)x0, wy = ys - (float)y0;
        const __half* b00 = base0 + ((size_t)(y0 * HH + x0) << 7);
        float v00 = __half2float(b00[tid]);
        float v01 = __half2float(b00[CC + tid]);
        float v10 = __half2float(b00[(HH << 7) + tid]);
        float v11 = __half2float(b00[(HH << 7) + CC + tid]);
        ob[588 + p * CC + tid] = v00 * (1.f - wx) * (1.f - wy) + v01 * wx * (1.f - wy)
                               + v10 * (1.f - wx) * wy + v11 * wx * wy;
    }
}

// ---------------------------------------------------------------------------
extern "C" void kernel_launch(void* const* d_in, const int* in_sizes, int n_in,
                              void* d_out, int out_size) {
    const float* fxy    = (const float*)d_in[0];
    const float* fyz    = (const float*)d_in[1];
    const float* fxz    = (const float*)d_in[2];
    const float* coords = (const float*)d_in[3];
    const int*   qt     = (const int*)d_in[4];
    float* out = (float*)d_out;

    // 1) fused transpose + L0/L1 (channels-last fp16)
    {
        dim3 grid(512, CC / 32, 3 * SS);
        transposeL1_kernel<<<grid, 256>>>(fxy, fyz, fxz);
    }
    // 2) fused L2 + L3 pools
    {
        dim3 grid(256, 3 * SS);
        pool23_kernel<<<grid, 256>>>();
    }
    // 3) init track features
    {
        dim3 grid(NN, 3);
        init_kernel<<<grid, CC>>>(coords, qt);
    }
    // 4) main correlation + feature sampling
    {
        dim3 grid(NN, SS, 3);
        main_kernel<<<grid, 128>>>(coords, out);
    }
}

// round 15
// speedup vs baseline: 1.1457x; 1.0693x over previous
#include <cuda_runtime.h>
#include <cuda_fp16.h>
#include <cstdint>

#define SS 8
#define NN 512
#define CC 128
#define HH 128

// Scratch: channels-last fp16 fmap pyramid per plane + fp32 scaled init feats.
__device__ __half g_P0[(size_t)3 * SS * HH * HH * CC];     // [3*S][128][128][C]
__device__ __half g_P1[(size_t)3 * SS * 64 * 64 * CC];
__device__ __half g_P2[(size_t)3 * SS * 32 * 32 * CC];
__device__ __half g_P3[(size_t)3 * SS * 16 * 16 * CC];
__device__ float  g_T [(size_t)3 * NN * CC];               // t / sqrt(C), fp32

__device__ __forceinline__ float2 h2f(uint32_t u) {
    return __half22float2(*(const __half2*)&u);
}

// ---------------------------------------------------------------------------
// Fused transpose + L1 pool. Tile = 32 channels x (2 rows x 16 px).
// ---------------------------------------------------------------------------
__global__ void __launch_bounds__(256) transposeL1_kernel(const float* __restrict__ fxy,
                                                          const float* __restrict__ fyz,
                                                          const float* __restrict__ fxz) {
    __shared__ float tile[32][33];    // [c][px], px = r*16 + j

    int ps = blockIdx.z;              // p*S + s
    int p = ps >> 3, s = ps & 7;
    const float* src = (p == 0 ? fxy : (p == 1 ? fyz : fxz)) + (size_t)s * CC * HH * HH;

    int c0 = blockIdx.y * 32;
    int mt = blockIdx.x;              // 0..511
    int rp = mt >> 3;                 // row pair 0..63
    int xt = (mt & 7) << 4;           // px base within row
    int t = threadIdx.x, lane = t & 31, w = t >> 5;

#pragma unroll
    for (int k = 0; k < 4; k++) {
        int c = w * 4 + k;
        int r = lane >> 4;
        int j = lane & 15;
        tile[c][r * 16 + j] = src[(size_t)(c0 + c) * (HH * HH) + (2 * rp + r) * HH + xt + j];
    }
    __syncthreads();

    {
        __half* d0 = g_P0 + (size_t)ps * HH * HH * CC;
#pragma unroll
        for (int k = 0; k < 4; k++) {
            int px = w * 4 + k;
            int r = px >> 4, j = px & 15;
            float v = tile[lane][px];
            size_t gpix = (size_t)(2 * rp + r) * HH + xt + j;
            d0[gpix * CC + c0 + lane] = __float2half(v);
        }
    }

    {
        __half* d1 = g_P1 + (size_t)ps * 64 * 64 * CC;
        int j1 = w;
        float v = (tile[lane][2 * j1] + tile[lane][2 * j1 + 1]
                 + tile[lane][16 + 2 * j1] + tile[lane][16 + 2 * j1 + 1]) * 0.25f;
        size_t gpix1 = (size_t)rp * 64 + (xt >> 1) + j1;
        d1[gpix1 * CC + c0 + lane] = __float2half(v);
    }
}

// ---------------------------------------------------------------------------
// Fused L2 + L3 pools from L1. Block = 4x4 L1-pixel tile x all 128 channels.
// ---------------------------------------------------------------------------
__global__ void __launch_bounds__(256) pool23_kernel() {
    __shared__ float s1[16][CC];
    __shared__ float s2[4][CC];

    int ps = blockIdx.y;
    int b = blockIdx.x;
    int by = b >> 4, bx = b & 15;
    const __half* src1 = g_P1 + (size_t)ps * 64 * 64 * CC;
    int t = threadIdx.x;

    {
        int px = t >> 4;
        int cg = (t & 15) * 8;
        int ly = px >> 2, lx = px & 3;
        const __half* q = src1 + ((size_t)((by * 4 + ly) * 64 + bx * 4 + lx)) * CC + cg;
        uint4 r = *(const uint4*)q;
        float2 f;
        f = h2f(r.x); s1[px][cg + 0] = f.x; s1[px][cg + 1] = f.y;
        f = h2f(r.y); s1[px][cg + 2] = f.x; s1[px][cg + 3] = f.y;
        f = h2f(r.z); s1[px][cg + 4] = f.x; s1[px][cg + 5] = f.y;
        f = h2f(r.w); s1[px][cg + 6] = f.x; s1[px][cg + 7] = f.y;
    }
    __syncthreads();

    {
        __half* d2 = g_P2 + (size_t)ps * 32 * 32 * CC;
#pragma unroll
        for (int it = 0; it < 2; it++) {
            int lin = it * 256 + t;
            int opx = lin >> 7;
            int c = lin & 127;
            int oy = opx >> 1, ox = opx & 1;
            int pA = (2 * oy) * 4 + 2 * ox;
            float v = (s1[pA][c] + s1[pA + 1][c] + s1[pA + 4][c] + s1[pA + 5][c]) * 0.25f;
            s2[opx][c] = v;
            d2[((size_t)((by * 2 + oy) * 32 + bx * 2 + ox)) * CC + c] = __float2half(v);
        }
    }
    __syncthreads();

    if (t < 128) {
        __half* d3 = g_P3 + (size_t)ps * 16 * 16 * CC;
        float v = (s2[0][t] + s2[1][t] + s2[2][t] + s2[3][t]) * 0.25f;
        d3[((size_t)(by * 16 + bx)) * CC + t] = __float2half(v);
    }
}

// ---------------------------------------------------------------------------
// Init track features (fp32 accumulate from fp16 P0), pre-scaled 1/sqrt(C)
// ---------------------------------------------------------------------------
__global__ void init_kernel(const float* __restrict__ coords,
                            const int* __restrict__ qt) {
    int n = blockIdx.x, p = blockIdx.y, c = threadIdx.x;
    float x = coords[n * 3 + 0], y = coords[n * 3 + 1], z = coords[n * 3 + 2];
    float u = (p == 0) ? x : (p == 1 ? y : x);
    float v = (p == 0) ? y : z;
    int f = qt[n];
    const __half* base = g_P0 + (size_t)(p * SS + f) * HH * HH * CC;

    u = fminf(fmaxf(u, 0.f), (float)(HH - 1));
    v = fminf(fmaxf(v, 0.f), (float)(HH - 1));
    int x0 = min(max((int)floorf(u), 0), HH - 2);
    int y0 = min(max((int)floorf(v), 0), HH - 2);
    float wx = u - (float)x0, wy = v - (float)y0;

    const __half* b00 = base + ((size_t)(y0 * HH + x0) << 7);
    float v00 = __half2float(b00[c]);
    float v01 = __half2float(b00[CC + c]);
    float v10 = __half2float(b00[(HH << 7) + c]);
    float v11 = __half2float(b00[(HH << 7) + CC + c]);
    float val = v00 * (1.f - wx) * (1.f - wy) + v01 * wx * (1.f - wy)
              + v10 * (1.f - wx) * wy + v11 * wx * wy;
    g_T[(size_t)(p * NN + n) * CC + c] = val * 0.08838834764831845f; // 1/sqrt(128)
}

// ---------------------------------------------------------------------------
// Main: block = (n, s, p). BALANCED mapping: warp w handles rows {2w, 2w+1}
// of EVERY level (uniform latency mix per warp -> no barrier imbalance).
// HFMA2 half2 dot partials + fold-pair reduction (lanes 0/4/8/12 hold
// j = 0/2/1/3).
// ---------------------------------------------------------------------------
__global__ void __launch_bounds__(128) main_kernel(const float* __restrict__ coords,
                                                   float* __restrict__ out) {
    int n = blockIdx.x;
    int s = 7 - blockIdx.y;                  // flipped traversal (L2-tail reuse)
    int p = 2 - blockIdx.z;
    int tid = threadIdx.x, lane = tid & 31, w = tid >> 5;
    int ps = p * SS + s;

    const float* cc = coords + (size_t)(s * NN + n) * 3;
    float x = cc[0], y = cc[1], z = cc[2];
    float u = (p == 0) ? x : (p == 1 ? y : x);
    float v = (p == 0) ? y : z;

    __shared__ float sT[CC];
    __shared__ float G[4][64];
    sT[tid] = g_T[(size_t)(p * NN + n) * CC + tid];
    __syncthreads();

    int li = lane & 15;
    int hp = lane >> 4;                       // half-warp position parity
    float4 tA = ((const float4*)sT)[li * 2];  // channels li*8 .. li*8+7
    float4 tB = ((const float4*)sT)[li * 2 + 1];
    __half2 t0 = __floats2half2_rn(tA.x, tA.y);
    __half2 t1 = __floats2half2_rn(tA.z, tA.w);
    __half2 t2 = __floats2half2_rn(tB.x, tB.y);
    __half2 t3 = __floats2half2_rn(tB.z, tB.w);

    // result-lane bookkeeping for the folded reduction:
    // lanes li in {0,4,8,12} end up holding j = {0,2,1,3}
    int q = li >> 2;
    int jm = ((q & 1) << 1) | (q >> 1);
    int gcol = 2 * jm + hp;                   // G column this lane may write
    bool isRes = (li & 3) == 0;
    bool b8 = (li & 8) != 0, b4 = (li & 4) != 0;

    const __half* base0 = g_P0 + (size_t)ps * HH * HH * CC;
    const __half* base1 = g_P1 + (size_t)ps * 64 * 64 * CC;
    const __half* base2 = g_P2 + (size_t)ps * 32 * 32 * CC;
    const __half* base3 = g_P3 + (size_t)ps * 16 * 16 * CC;

    // ---- grid phase: warp w handles rows 2w, 2w+1 of every level ----
#pragma unroll
    for (int l = 0; l < 4; l++) {
        const int Wl = HH >> l;
        const float sc = 1.0f / (float)(1 << l);
        const __half* base = (l == 0) ? base0 : (l == 1) ? base1 : (l == 2) ? base2 : base3;

        float cx = u * sc, cy = v * sc;
        int bx = (int)floorf(cx), by = (int)floorf(cy);

        // 4 named clamped column offsets for this half-warp (cols 2j+hp)
        int co0 = min(max(bx - 3 + hp, 0), Wl - 1) * CC;
        int co1 = min(max(bx - 1 + hp, 0), Wl - 1) * CC;
        int co2 = min(max(bx + 1 + hp, 0), Wl - 1) * CC;
        int co3 = min(max(bx + 3 + hp, 0), Wl - 1) * CC;
        const __half* lb = base + (li << 3);
        const int rowStride = Wl * CC;

#pragma unroll
        for (int rr = 0; rr < 2; rr++) {
            int r = 2 * w + rr;
            int gy = min(max(by - 3 + r, 0), Wl - 1);
            const __half* rb = lb + gy * rowStride;

            union { uint4 u4; __half2 h[4]; } r0, r1, r2, r3;
            r0.u4 = *(const uint4*)(rb + co0);
            r1.u4 = *(const uint4*)(rb + co1);
            r2.u4 = *(const uint4*)(rb + co2);
            r3.u4 = *(const uint4*)(rb + co3);

            __half2 a0 = __hmul2(r0.h[0], t0);
            a0 = __hfma2(r0.h[1], t1, a0); a0 = __hfma2(r0.h[2], t2, a0); a0 = __hfma2(r0.h[3], t3, a0);
            __half2 a1 = __hmul2(r1.h[0], t0);
            a1 = __hfma2(r1.h[1], t1, a1); a1 = __hfma2(r1.h[2], t2, a1); a1 = __hfma2(r1.h[3], t3, a1);
            __half2 a2 = __hmul2(r2.h[0], t0);
            a2 = __hfma2(r2.h[1], t1, a2); a2 = __hfma2(r2.h[2], t2, a2); a2 = __hfma2(r2.h[3], t3, a2);
            __half2 a3 = __hmul2(r3.h[0], t0);
            a3 = __hfma2(r3.h[1], t1, a3); a3 = __hfma2(r3.h[2], t2, a3); a3 = __hfma2(r3.h[3], t3, a3);

            float d0 = __low2float(a0) + __high2float(a0);
            float d1 = __low2float(a1) + __high2float(a1);
            float d2 = __low2float(a2) + __high2float(a2);
            float d3 = __low2float(a3) + __high2float(a3);

            // fold-pair reduction over 16 lanes (xor < 16: half-warps independent)
            float sA = __shfl_xor_sync(0xffffffffu, b8 ? d0 : d1, 8);
            float aa = (b8 ? d1 : d0) + sA;
            float sB = __shfl_xor_sync(0xffffffffu, b8 ? d2 : d3, 8);
            float bb = (b8 ? d3 : d2) + sB;
            float sC = __shfl_xor_sync(0xffffffffu, b4 ? aa : bb, 4);
            float cval = (b4 ? bb : aa) + sC;
            cval += __shfl_xor_sync(0xffffffffu, cval, 2);
            cval += __shfl_xor_sync(0xffffffffu, cval, 1);

            if (isRes) G[l][r * 8 + gcol] = cval;
        }
    }
    __syncthreads();

    float* ob = out + ((size_t)s * NN + n) * 972;

    // ---- tap phase: 196 taps over 128 threads ----
#pragma unroll
    for (int t = tid; t < 196; t += 128) {
        int l = t / 49, k = t % 49;
        int Wl = HH >> l;
        float sc = (l == 0) ? 1.f : (l == 1) ? 0.5f : (l == 2) ? 0.25f : 0.125f;
        float cx = u * sc, cy = v * sc;
        int bx = (int)floorf(cx), by = (int)floorf(cy);
        int kx = k % 7, ky = k / 7;
        float xs = fminf(fmaxf(cx + (float)(kx - 3), 0.f), (float)(Wl - 1));
        float ys = fminf(fmaxf(cy + (float)(ky - 3), 0.f), (float)(Wl - 1));
        int x0 = min(max((int)floorf(xs), 0), Wl - 2);
        int y0 = min(max((int)floorf(ys), 0), Wl - 2);
        float wx = xs - (float)x0, wy = ys - (float)y0;
        int j = x0 - bx + 3;   // in [0,6], j+1 <= 7 (clamp cases verified)
        int i = y0 - by + 3;
        float g00 = G[l][i * 8 + j];
        float g01 = G[l][i * 8 + j + 1];
        float g10 = G[l][i * 8 + 8 + j];
        float g11 = G[l][i * 8 + 8 + j + 1];
        ob[p * 196 + t] = g00 * (1.f - wx) * (1.f - wy) + g01 * wx * (1.f - wy)
                        + g10 * (1.f - wx) * wy + g11 * wx * wy;
    }

    // ---- full-res feature bilinear sample (thread = channel) ----
    {
        float xs = fminf(fmaxf(u, 0.f), (float)(HH - 1));
        float ys = fminf(fmaxf(v, 0.f), (float)(HH - 1));
        int x0 = min(max((int)floorf(xs), 0), HH - 2);
        int y0 = min(max((int)floorf(ys), 0), HH - 2);
        float wx = xs - (float)x0, wy = ys - (float)y0;
        const __half* b00 = base0 + ((size_t)(y0 * HH + x0) << 7);
        float v00 = __half2float(b00[tid]);
        float v01 = __half2float(b00[CC + tid]);
        float v10 = __half2float(b00[(HH << 7) + tid]);
        float v11 = __half2float(b00[(HH << 7) + CC + tid]);
        ob[588 + p * CC + tid] = v00 * (1.f - wx) * (1.f - wy) + v01 * wx * (1.f - wy)
                               + v10 * (1.f - wx) * wy + v11 * wx * wy;
    }
}

// ---------------------------------------------------------------------------
extern "C" void kernel_launch(void* const* d_in, const int* in_sizes, int n_in,
                              void* d_out, int out_size) {
    const float* fxy    = (const float*)d_in[0];
    const float* fyz    = (const float*)d_in[1];
    const float* fxz    = (const float*)d_in[2];
    const float* coords = (const float*)d_in[3];
    const int*   qt     = (const int*)d_in[4];
    float* out = (float*)d_out;

    // 1) fused transpose + L0/L1 (channels-last fp16)
    {
        dim3 grid(512, CC / 32, 3 * SS);
        transposeL1_kernel<<<grid, 256>>>(fxy, fyz, fxz);
    }
    // 2) fused L2 + L3 pools
    {
        dim3 grid(256, 3 * SS);
        pool23_kernel<<<grid, 256>>>();
    }
    // 3) init track features
    {
        dim3 grid(NN, 3);
        init_kernel<<<grid, CC>>>(coords, qt);
    }
    // 4) main correlation + feature sampling
    {
        dim3 grid(NN, SS, 3);
        main_kernel<<<grid, 128>>>(coords, out);
    }
}